// round 7
// baseline (speedup 1.0000x reference)
#include <cuda_runtime.h>
#include <stdint.h>
#include <math.h>

#define N_PTS   32768
#define KCODES  2048
#define DIM     128
#define BM      128
#define BN      32
#define NTILES  (KCODES / BN)        // 64
#define TEMP_INV (1.0f/0.9f)

// Scratch (allocation-free rule: __device__ globals)
__device__ float g_conf[(size_t)N_PTS * KCODES];   // 256 MB conf' spill
__device__ float g_esq[KCODES];
__device__ float g_clsum[KCODES];
__device__ float g_bfrag[KCODES * DIM];            // B raw fp32, fragment order, tile-major

__device__ __forceinline__ float tf32r(float a) {
    float r;
    asm("cvt.rna.tf32.f32 %0, %1;" : "=f"(r) : "f"(a));
    return r;
}

__device__ __forceinline__ void cp_async16(uint32_t saddr, const void* gptr) {
    asm volatile("cp.async.cg.shared.global [%0], [%1], 16;" :: "r"(saddr), "l"(gptr));
}

#define MMA_TF32(d, a, b) \
    asm volatile("mma.sync.aligned.m16n8k8.row.col.f32.tf32.tf32.f32 " \
        "{%0,%1,%2,%3},{%4,%5,%6,%7},{%8,%9},{%0,%1,%2,%3};" \
        : "+f"((d)[0]), "+f"((d)[1]), "+f"((d)[2]), "+f"((d)[3]) \
        : "r"(__float_as_uint((a)[0])), "r"(__float_as_uint((a)[1])), \
          "r"(__float_as_uint((a)[2])), "r"(__float_as_uint((a)[3])), \
          "r"(__float_as_uint((b)[0])), "r"(__float_as_uint((b)[1])))

// ---------------------------------------------------------------------------
// Kernel 1: e_sq per code (warp per code), zero class accumulators, and
// write embed into RAW fp32 MMA-fragment order, tile-major (BN=32).
// ---------------------------------------------------------------------------
__global__ void prep_kernel(const float* __restrict__ embed) {
    const int tid  = blockIdx.x * blockDim.x + threadIdx.x;  // 0..65535
    const int lane = tid & 31;
    const int warp = tid >> 5;
    if (tid < KCODES) g_clsum[tid] = 0.f;

    // e_sq
    {
        const float* row = embed + (size_t)warp * DIM;
        float s = 0.f;
        #pragma unroll
        for (int i = 0; i < 4; ++i) { float v = row[lane + 32 * i]; s = fmaf(v, v, s); }
        #pragma unroll
        for (int o = 16; o > 0; o >>= 1) s += __shfl_down_sync(0xffffffffu, s, o);
        if (lane == 0) g_esq[warp] = s;
    }

    // B fragment-order scatter: one float4 (4 consecutive k) per thread
    {
        float4 v = ((const float4*)embed)[tid];
        const int n   = tid >> 5;          // code row
        const int k4  = tid & 31;          // float4 index along k
        const int ct  = n >> 5;
        const int wn  = (n >> 4) & 1;
        const int nt  = (n >> 3) & 1;
        const int gid = n & 7;
        const int ks  = k4 >> 1;
        const int slot = k4 & 1;
        float a4[4] = {v.x, v.y, v.z, v.w};
        #pragma unroll
        for (int j = 0; j < 4; ++j) {
            size_t o = (size_t)ct * 4096 +
                       ((size_t)(((wn * 2 + nt) * 16 + ks) * 32 + gid * 4 + j)) * 2 + slot;
            g_bfrag[o] = a4[j];
        }
    }
}

// ---------------------------------------------------------------------------
// Kernel 2: 3xTF32 GEMM (split-at-load) + argmax + gather + fused cooperative
// softmax. smem 96KB -> 2 CTAs/SM, 256 CTAs = 1 wave.
//   a_s   [16384] raw A fp32, fragment order (64KB)
//   b_st  [2][4096] raw B stages (32KB)
// ---------------------------------------------------------------------------
__global__ void __launch_bounds__(256, 2)
gemm_kernel(const float* __restrict__ x,
            const float* __restrict__ embed,
            float* __restrict__ out_q,
            float* __restrict__ out_ind) {
    extern __shared__ float sm[];
    float* a_s  = sm;                  // 16384 floats
    float* b_st = sm + 16384;          // 2 * 4096 floats

    const int tid  = threadIdx.x;
    const int lane = tid & 31;
    const int w    = tid >> 5;
    const int wm   = w >> 1;          // 0..3: 32-point slab
    const int wn   = w & 1;           // 0..1: 16-code slab
    const int n0   = blockIdx.x * BM;

    const uint32_t b_st_s = (uint32_t)__cvta_generic_to_shared(b_st);

    // ---- issue B tile 0 copy ----
    {
        const float4* g4 = (const float4*)g_bfrag;
        #pragma unroll
        for (int i = 0; i < 4; ++i)
            cp_async16(b_st_s + (i * 256 + tid) * 16, &g4[i * 256 + tid]);
        asm volatile("cp.async.commit_group;");
    }

    // ---- A (x scaled by 2, exact) raw into fragment order ----
    {
        const float4* x4 = (const float4*)(x + (size_t)n0 * DIM);
        #pragma unroll
        for (int t = 0; t < 16; ++t) {
            int idx = t * 256 + tid;
            int m  = idx >> 5;
            int k4 = idx & 31;
            float4 v = x4[idx];
            float a4[4] = {2.f * v.x, 2.f * v.y, 2.f * v.z, 2.f * v.w};
            int r    = m & 15;
            int base = (((m >> 4) * 16 + (k4 >> 1)) * 32) * 4;
            int sl   = (r >> 3) + ((k4 & 1) << 1);
            #pragma unroll
            for (int j = 0; j < 4; ++j)
                a_s[base + ((r & 7) * 4 + j) * 4 + sl] = a4[j];
        }
    }

    float runv[4];
    int   runi[4];
    #pragma unroll
    for (int i = 0; i < 4; ++i) { runv[i] = -3.0e38f; runi[i] = 0; }

    for (int ct = 0; ct < NTILES; ++ct) {
        // issue next tile into other stage, then wait for current stage
        if (ct + 1 < NTILES) {
            const float4* g4 = (const float4*)(g_bfrag + (size_t)(ct + 1) * 4096);
            uint32_t dst = b_st_s + (uint32_t)(((ct + 1) & 1) * 16384);
            #pragma unroll
            for (int i = 0; i < 4; ++i)
                cp_async16(dst + (i * 256 + tid) * 16, &g4[i * 256 + tid]);
            asm volatile("cp.async.commit_group;");
            asm volatile("cp.async.wait_group 1;");
        } else {
            asm volatile("cp.async.wait_group 0;");
        }
        __syncthreads();                      // stage (ct&1) visible to all warps

        const float* b_raw = b_st + (ct & 1) * 4096;

        float acc[2][2][4];
        #pragma unroll
        for (int mt = 0; mt < 2; ++mt)
            #pragma unroll
            for (int nt = 0; nt < 2; ++nt)
                #pragma unroll
                for (int r = 0; r < 4; ++r) acc[mt][nt][r] = 0.f;

        #pragma unroll
        for (int ks = 0; ks < 16; ++ks) {
            float ah[2][4], al[2][4];
            #pragma unroll
            for (int mt = 0; mt < 2; ++mt) {
                int ab = (((wm * 2 + mt) * 16 + ks) * 32 + lane) * 4;
                float4 ar = *(const float4*)&a_s[ab];
                ah[mt][0] = tf32r(ar.x); al[mt][0] = tf32r(ar.x - ah[mt][0]);
                ah[mt][1] = tf32r(ar.y); al[mt][1] = tf32r(ar.y - ah[mt][1]);
                ah[mt][2] = tf32r(ar.z); al[mt][2] = tf32r(ar.z - ah[mt][2]);
                ah[mt][3] = tf32r(ar.w); al[mt][3] = tf32r(ar.w - ah[mt][3]);
            }
            float bh[2][2], bl[2][2];
            #pragma unroll
            for (int nt = 0; nt < 2; ++nt) {
                int bb = (((wn * 2 + nt) * 16 + ks) * 32 + lane) * 2;
                float2 br = *(const float2*)&b_raw[bb];
                bh[nt][0] = tf32r(br.x); bl[nt][0] = tf32r(br.x - bh[nt][0]);
                bh[nt][1] = tf32r(br.y); bl[nt][1] = tf32r(br.y - bh[nt][1]);
            }
            #pragma unroll
            for (int mt = 0; mt < 2; ++mt)
                #pragma unroll
                for (int nt = 0; nt < 2; ++nt) {
                    MMA_TF32(acc[mt][nt], ah[mt], bh[nt]);   // hi*hi
                    MMA_TF32(acc[mt][nt], ah[mt], bl[nt]);   // hi*lo
                    MMA_TF32(acc[mt][nt], al[mt], bh[nt]);   // lo*hi
                }
        }

        // ---- epilogue: conf = acc - esq, argmax (ascending code), spill ----
        const int c0 = ct * BN;
        #pragma unroll
        for (int nt = 0; nt < 2; ++nt) {
            int cb = c0 + wn * 16 + nt * 8 + 2 * (lane & 3);
            float e0 = __ldg(&g_esq[cb]);
            float e1 = __ldg(&g_esq[cb + 1]);
            #pragma unroll
            for (int mt = 0; mt < 2; ++mt) {
                #pragma unroll
                for (int h = 0; h < 2; ++h) {
                    int slot = mt * 2 + h;
                    int row  = n0 + wm * 32 + mt * 16 + (lane >> 2) + h * 8;
                    float v0 = acc[mt][nt][2 * h + 0] - e0;
                    float v1 = acc[mt][nt][2 * h + 1] - e1;
                    if (v0 > runv[slot]) { runv[slot] = v0; runi[slot] = cb; }
                    if (v1 > runv[slot]) { runv[slot] = v1; runi[slot] = cb + 1; }
                    *(float2*)&g_conf[(size_t)row * KCODES + cb] = make_float2(v0, v1);
                }
            }
        }
        __syncthreads();                      // all warps done with stage before overwrite
    }

    // ---- cross-thread argmax reduction (B-region smem reuse) ----
    float* red_v  = b_st;                      // [BM][8]  floats +0..1023
    int*   red_i  = (int*)(b_st + 1024);       // [BM][8]        +1024..2047
    int*   sidx   = (int*)(b_st + 2048);       // [BM]           +2048..2175
    float* maxv_s = b_st + 2176;               // [BM]           +2176..2303
    float* bins_s = b_st + 2304;               // [KCODES]       +2304..4351
    #pragma unroll
    for (int mt = 0; mt < 2; ++mt)
        #pragma unroll
        for (int h = 0; h < 2; ++h) {
            int slot = mt * 2 + h;
            int rloc = wm * 32 + mt * 16 + (lane >> 2) + h * 8;
            int cidx = wn * 4 + (lane & 3);
            red_v[rloc * 8 + cidx] = runv[slot];
            red_i[rloc * 8 + cidx] = runi[slot];
        }
    __syncthreads();
    if (tid < BM) {
        float bv = red_v[tid * 8];
        int   bi = red_i[tid * 8];
        #pragma unroll
        for (int t = 1; t < 8; ++t) {
            float v  = red_v[tid * 8 + t];
            int   ii = red_i[tid * 8 + t];
            if (v > bv || (v == bv && ii < bi)) { bv = v; bi = ii; }
        }
        maxv_s[tid]       = bv;
        sidx[tid]         = bi;
        out_ind[n0 + tid] = (float)bi;
    }
    __syncthreads();

    // ---- fused gather + zero class bins ----
    {
        const float4* e4 = (const float4*)embed;
        float4*       q4 = (float4*)out_q;
        for (int p = w; p < BM; p += 8) {
            int idx = sidx[p];
            q4[(size_t)(n0 + p) * 32 + lane] = e4[(size_t)idx * 32 + lane];
        }
        for (int k = tid; k < KCODES; k += 256) bins_s[k] = 0.f;
    }
    __syncthreads();

    // ---- fused cooperative softmax: 8 points/iter, exps staged in smem
    // (A region reused as eb[8][KCODES]), ownership bins (no atomics). ----
    {
        float* eb   = a_s;                     // 16384 floats (A done)
        float* zinv = b_st + 4352;             // [8]
        for (int it = 0; it < BM / 8; ++it) {
            const int pl = it * 8 + w;
            const float m = maxv_s[pl];
            const float4* row4 = (const float4*)&g_conf[(size_t)(n0 + pl) * KCODES];

            float z = 0.f;
            #pragma unroll
            for (int j = 0; j < 16; ++j) {
                int k4 = j * 32 + lane;
                float4 c = row4[k4];
                float e0 = __expf((c.x - m) * TEMP_INV);
                float e1 = __expf((c.y - m) * TEMP_INV);
                float e2 = __expf((c.z - m) * TEMP_INV);
                float e3 = __expf((c.w - m) * TEMP_INV);
                *(float4*)&eb[w * KCODES + k4 * 4] = make_float4(e0, e1, e2, e3);
                z += (e0 + e1) + (e2 + e3);
            }
            #pragma unroll
            for (int o = 16; o > 0; o >>= 1) z += __shfl_xor_sync(0xffffffffu, z, o);
            if (lane == 0) zinv[w] = 1.f / z;  // z >= 1 (argmax term present)
            __syncthreads();

            for (int k = tid; k < KCODES; k += 256) {
                float s = 0.f;
                #pragma unroll
                for (int ww = 0; ww < 8; ++ww) s = fmaf(eb[ww * KCODES + k], zinv[ww], s);
                bins_s[k] += s;
            }
            __syncthreads();
        }
    }
    for (int k = tid; k < KCODES; k += 256) atomicAdd(&g_clsum[k], bins_s[k]);
}

// ---------------------------------------------------------------------------
// Kernel 3: diversity loss = sum_k p_k * log(p_k + eps).
// ---------------------------------------------------------------------------
__global__ void loss_kernel(float* __restrict__ out_loss) {
    __shared__ float red[256];
    const int tid = threadIdx.x;
    float acc = 0.f;
    for (int k = tid; k < KCODES; k += 256) {
        float p = g_clsum[k] * (1.0f / (float)N_PTS);
        acc += p * logf(p + 1e-6f);
    }
    red[tid] = acc;
    __syncthreads();
    for (int s = 128; s > 0; s >>= 1) {
        if (tid < s) red[tid] += red[tid + s];
        __syncthreads();
    }
    if (tid == 0) *out_loss = red[0];
}

// ---------------------------------------------------------------------------
extern "C" void kernel_launch(void* const* d_in, const int* in_sizes, int n_in,
                              void* d_out, int out_size) {
    const float* x     = (const float*)d_in[0];
    const float* embed = (const float*)d_in[1];
    float* out      = (float*)d_out;
    float* out_q    = out;                                   // N*DIM
    float* out_ind  = out + (size_t)N_PTS * DIM;             // N
    float* out_loss = out + (size_t)N_PTS * DIM + N_PTS;     // 1

    const int gemm_smem = (16384 + 2 * 4096) * (int)sizeof(float);   // 96 KB
    cudaFuncSetAttribute(gemm_kernel, cudaFuncAttributeMaxDynamicSharedMemorySize, gemm_smem);

    prep_kernel <<<256, 256>>>(embed);
    gemm_kernel <<<N_PTS / BM, 256, gemm_smem>>>(x, embed, out_q, out_ind);
    loss_kernel <<<1, 256>>>(out_loss);
}